// round 16
// baseline (speedup 1.0000x reference)
#include <cuda_runtime.h>
#include <cuda_bf16.h>
#include <cstdint>

// Conv1dLocal via mma.sync bf16 split-precision (sm_100-safe, no tcgen05).
// out[b,o,s] = sum_{i,k} x[b,i,s+k]*w[o,i,s,k]; per-s GEMM M=64(o) N=32(b) K=448.
// Round-14b (resubmit): STILE=2, 256 threads, 4 warps per s-GEMM (M=16 slice),
// grid 256, smem 88KB -> 2 CTAs/SM. Same verified fragment/swizzle math as R13.
// w staged with cp8 (56B*blockIdx.x source offset is only 8B-aligned).
// K streamed as 8 i-chunks of 8 (kk = 8*il + k, slot7 zero -> K'=64, 4 ksteps).
// Split: w=wh+wl, x=xh+xl; D = wh*xh + wl*xh + wh*xl (ll dropped).

#define B_    32
#define IC_   64
#define OC_   64
#define S_    512
#define KW_   7
#define L_    518

#define STILE     2
#define NCHUNK    8
#define ICHUNK    8
#define THREADS   256

// smem offsets (bytes)
#define A_TILE    (64 * 128)            // 8192 per (term, s)
#define B_TILE    (32 * 128)            // 4096 per (term, s)
#define SM_A      0                      // hi A tiles [sg]
#define SM_A_LO   (2 * A_TILE)           // 16384
#define SM_B      (4 * A_TILE)           // 32768 : hi B tiles [sg]
#define SM_B_LO   (SM_B + 2 * B_TILE)    // 40960
#define SM_RAWW   (SM_B + 4 * B_TILE)    // 49152 : 512 runs x 64B (56 used)
#define SM_RAWX   (SM_RAWW + 512 * 64)   // 81920 : 256 runs x 32B
#define SMEM_TOTAL (SM_RAWX + 256 * 32)  // 90112

__device__ __forceinline__ void cp8(unsigned dst, const void* src) {
    asm volatile("cp.async.ca.shared.global [%0], [%1], 8;" :: "r"(dst), "l"(src));
}
__device__ __forceinline__ void ldsm4(unsigned addr, unsigned &r0, unsigned &r1,
                                      unsigned &r2, unsigned &r3) {
    asm volatile("ldmatrix.sync.aligned.m8n8.x4.shared.b16 {%0,%1,%2,%3}, [%4];"
                 : "=r"(r0), "=r"(r1), "=r"(r2), "=r"(r3) : "r"(addr));
}
__device__ __forceinline__ void mma16816(float* c, unsigned a0, unsigned a1,
                                         unsigned a2, unsigned a3,
                                         unsigned b0, unsigned b1) {
    asm volatile(
        "mma.sync.aligned.m16n8k16.row.col.f32.bf16.bf16.f32 "
        "{%0,%1,%2,%3}, {%4,%5,%6,%7}, {%8,%9}, {%0,%1,%2,%3};"
        : "+f"(c[0]), "+f"(c[1]), "+f"(c[2]), "+f"(c[3])
        : "r"(a0), "r"(a1), "r"(a2), "r"(a3), "r"(b0), "r"(b1));
}

__global__ __launch_bounds__(THREADS, 2)
void conv1d_local_mma(const float* __restrict__ x,
                      const float* __restrict__ w,
                      float* __restrict__ out)
{
    extern __shared__ char smem[];
    const unsigned smem_u = (unsigned)__cvta_generic_to_shared(smem);
    const int tid  = threadIdx.x;
    const int lane = tid & 31;
    const int warp = tid >> 5;
    const int sg   = warp >> 2;          // s within CTA (0..1)
    const int q    = warp & 3;           // M-slice (rows q*16 .. q*16+15)
    const int s0   = blockIdx.x * STILE;

    float* rawW = reinterpret_cast<float*>(smem + SM_RAWW);
    float* rawX = reinterpret_cast<float*>(smem + SM_RAWX);

    // ---- stage(c): cp.async chunk c raw data (all 8B-granular, 8B-aligned)
    auto stage = [&](int c) {
        // w: 512 runs (o, il), 14 floats = 7 x cp8; 2 runs/thread
        #pragma unroll
        for (int m = 0; m < 2; ++m) {
            int r = tid + THREADS * m;
            int o = r >> 3, il = r & 7;
            int i = c * ICHUNK + il;
            const float* src = w + (((size_t)(o * IC_ + i) * S_ + s0) * KW_);
            unsigned dst = smem_u + SM_RAWW + r * 64;
            #pragma unroll
            for (int p = 0; p < 7; ++p)
                cp8(dst + p * 8, src + p * 2);
        }
        // x: 256 runs (b, il), 8 floats = 4 x cp8; 1 run/thread
        {
            int r = tid;
            int b = r >> 3, il = r & 7;
            int i = c * ICHUNK + il;
            const float* src = x + ((size_t)(b * IC_ + i) * L_ + s0);
            unsigned dst = smem_u + SM_RAWX + r * 32;
            #pragma unroll
            for (int p = 0; p < 4; ++p)
                cp8(dst + p * 8, src + p * 2);
        }
        asm volatile("cp.async.commit_group;");
    };

    stage(0);

    float acc[4][4];
    #pragma unroll
    for (int a = 0; a < 4; ++a)
        #pragma unroll
        for (int qq = 0; qq < 4; ++qq) acc[a][qq] = 0.f;

    const unsigned Ah = smem_u + SM_A    + sg * A_TILE;
    const unsigned Al = smem_u + SM_A_LO + sg * A_TILE;
    const unsigned Bh = smem_u + SM_B    + sg * B_TILE;
    const unsigned Bl = smem_u + SM_B_LO + sg * B_TILE;

    #pragma unroll 1
    for (int c = 0; c < NCHUNK; ++c) {
        asm volatile("cp.async.wait_group 0;");
        __syncthreads();   // raw(c) visible; all warps done with tiles(c-1)

        // ---- cvt w raw -> A hi/lo tiles. 1024 tasks (run, sl); 4/thread
        #pragma unroll
        for (int j = 0; j < 4; ++j) {
            int t  = tid + THREADS * j;
            int sl = t & 1;
            int r  = t >> 1;            // 0..511
            int o  = r >> 3, il = r & 7;
            const float* v = rawW + r * 16 + sl * 7;
            unsigned short uh[8], ul[8];
            #pragma unroll
            for (int k = 0; k < 7; ++k) {
                float f = v[k];
                __nv_bfloat16 h = __float2bfloat16(f);
                __nv_bfloat16 l = __float2bfloat16(f - __bfloat162float(h));
                uh[k] = __bfloat16_as_ushort(h);
                ul[k] = __bfloat16_as_ushort(l);
            }
            uh[7] = 0; ul[7] = 0;
            unsigned off = (unsigned)(sl * A_TILE + o * 128 + ((il ^ (o & 7)) << 4));
            char* ph = smem + SM_A    + off;
            char* pl = smem + SM_A_LO + off;
            #pragma unroll
            for (int n = 0; n < 4; ++n) {
                int j2 = (tid + n) & 3;   // bank stagger
                unsigned wh2 = (unsigned)uh[2*j2] | ((unsigned)uh[2*j2+1] << 16);
                unsigned wl2 = (unsigned)ul[2*j2] | ((unsigned)ul[2*j2+1] << 16);
                *reinterpret_cast<unsigned*>(ph + 4*j2) = wh2;
                *reinterpret_cast<unsigned*>(pl + 4*j2) = wl2;
            }
        }
        // ---- cvt x raw -> B hi/lo tiles. 512 tasks; 2/thread
        #pragma unroll
        for (int j = 0; j < 2; ++j) {
            int t  = tid + THREADS * j;
            int sl = t & 1;
            int r  = t >> 1;            // 0..255
            int b  = r >> 3, il = r & 7;
            const float* v = rawX + r * 8 + sl;
            unsigned short uh[8], ul[8];
            #pragma unroll
            for (int k = 0; k < 7; ++k) {
                float f = v[k];
                __nv_bfloat16 h = __float2bfloat16(f);
                __nv_bfloat16 l = __float2bfloat16(f - __bfloat162float(h));
                uh[k] = __bfloat16_as_ushort(h);
                ul[k] = __bfloat16_as_ushort(l);
            }
            uh[7] = 0; ul[7] = 0;
            unsigned off = (unsigned)(sl * B_TILE + b * 128 + ((il ^ (b & 7)) << 4));
            char* ph = smem + SM_B    + off;
            char* pl = smem + SM_B_LO + off;
            #pragma unroll
            for (int n = 0; n < 4; ++n) {
                int j2 = (tid + n) & 3;
                unsigned wh2 = (unsigned)uh[2*j2] | ((unsigned)uh[2*j2+1] << 16);
                unsigned wl2 = (unsigned)ul[2*j2] | ((unsigned)ul[2*j2+1] << 16);
                *reinterpret_cast<unsigned*>(ph + 4*j2) = wh2;
                *reinterpret_cast<unsigned*>(pl + 4*j2) = wl2;
            }
        }
        __syncthreads();   // tiles(c) ready; raw fully consumed

        if (c + 1 < NCHUNK) stage(c + 1);   // overlaps with mma below

        // ---- mma phase: warp's 16-row slice of s-GEMM sg, K'=64 -> 4 ksteps
        #pragma unroll
        for (int ks = 0; ks < 4; ++ks) {
            unsigned bh[8], bl[8];
            #pragma unroll
            for (int nt2 = 0; nt2 < 2; ++nt2) {
                int row = nt2 * 16 + ((lane >> 4) << 3) + (lane & 7);
                int ch  = 2 * ks + ((lane >> 3) & 1);
                unsigned byte = (unsigned)(row * 128 + ((ch ^ (row & 7)) << 4));
                ldsm4(Bh + byte, bh[nt2*4+0], bh[nt2*4+1], bh[nt2*4+2], bh[nt2*4+3]);
                ldsm4(Bl + byte, bl[nt2*4+0], bl[nt2*4+1], bl[nt2*4+2], bl[nt2*4+3]);
            }
            {
                int row = q * 16 + (lane & 15);
                int ch  = 2 * ks + (lane >> 4);
                unsigned byte = (unsigned)(row * 128 + ((ch ^ (row & 7)) << 4));
                unsigned a0, a1, a2, a3, c0, c1, c2, c3;
                ldsm4(Ah + byte, a0, a1, a2, a3);
                ldsm4(Al + byte, c0, c1, c2, c3);
                #pragma unroll
                for (int nt = 0; nt < 4; ++nt) {
                    unsigned b0 = bh[nt*2], b1 = bh[nt*2+1];
                    unsigned e0 = bl[nt*2], e1 = bl[nt*2+1];
                    mma16816(acc[nt], a0, a1, a2, a3, b0, b1); // wh*xh
                    mma16816(acc[nt], c0, c1, c2, c3, b0, b1); // wl*xh
                    mma16816(acc[nt], a0, a1, a2, a3, e0, e1); // wh*xl
                }
            }
        }
    }

    // ---- epilogue: direct STG, full coverage
    const int s_g  = s0 + sg;
    const int row0 = q * 16 + (lane >> 2);
    #pragma unroll
    for (int nt = 0; nt < 4; ++nt) {
        int col0 = nt * 8 + (lane & 3) * 2;
        out[(size_t)(col0    ) * (OC_ * S_) + (size_t)(row0    ) * S_ + s_g] = acc[nt][0];
        out[(size_t)(col0 + 1) * (OC_ * S_) + (size_t)(row0    ) * S_ + s_g] = acc[nt][1];
        out[(size_t)(col0    ) * (OC_ * S_) + (size_t)(row0 + 8) * S_ + s_g] = acc[nt][2];
        out[(size_t)(col0 + 1) * (OC_ * S_) + (size_t)(row0 + 8) * S_ + s_g] = acc[nt][3];
    }
}

extern "C" void kernel_launch(void* const* d_in, const int* in_sizes, int n_in,
                              void* d_out, int out_size)
{
    const float* x = (const float*)d_in[0];
    const float* w = (const float*)d_in[1];
    float* out = (float*)d_out;

    cudaFuncSetAttribute(conv1d_local_mma,
                         cudaFuncAttributeMaxDynamicSharedMemorySize, SMEM_TOTAL);

    conv1d_local_mma<<<S_ / STILE, THREADS, SMEM_TOTAL>>>(x, w, out);
}

// round 17
// speedup vs baseline: 1.2636x; 1.2636x over previous
#include <cuda_runtime.h>
#include <cuda_bf16.h>
#include <cstdint>

// Conv1dLocal via mma.sync bf16 split-precision (sm_100-safe).
// Round-17: NO raw smem staging. cvt loads gmem directly (__ldg float2),
// converts, stores to swizzled bf16 tiles. smem = tiles only (48KB) ->
// 3 CTAs/SM, three independent phase schedules hide LDG latency.
// STILE=2, 256 threads, grid 256. 4 warps per s-GEMM (M=16 slice each).
// K streamed as 8 i-chunks of 8 (kk = 8*il + k, slot7 zero -> K'=64, 4 ksteps).
// Split: w=wh+wl, x=xh+xl; D = wh*xh + wl*xh + wh*xl (ll dropped).
// Fragment/swizzle math identical to the R13-verified kernel.

#define B_    32
#define IC_   64
#define OC_   64
#define S_    512
#define KW_   7
#define L_    518

#define STILE     2
#define NCHUNK    8
#define ICHUNK    8
#define THREADS   256

#define A_TILE    (64 * 128)             // 8192 per (term, s)
#define B_TILE    (32 * 128)             // 4096 per (term, s)
#define SM_A      0                       // hi A tiles [sg]
#define SM_A_LO   (2 * A_TILE)            // 16384
#define SM_B      (4 * A_TILE)            // 32768 : hi B tiles [sg]
#define SM_B_LO   (SM_B + 2 * B_TILE)     // 40960
#define SMEM_TOTAL (SM_B + 4 * B_TILE)    // 49152

__device__ __forceinline__ void ldsm4(unsigned addr, unsigned &r0, unsigned &r1,
                                      unsigned &r2, unsigned &r3) {
    asm volatile("ldmatrix.sync.aligned.m8n8.x4.shared.b16 {%0,%1,%2,%3}, [%4];"
                 : "=r"(r0), "=r"(r1), "=r"(r2), "=r"(r3) : "r"(addr));
}
__device__ __forceinline__ void mma16816(float* c, unsigned a0, unsigned a1,
                                         unsigned a2, unsigned a3,
                                         unsigned b0, unsigned b1) {
    asm volatile(
        "mma.sync.aligned.m16n8k16.row.col.f32.bf16.bf16.f32 "
        "{%0,%1,%2,%3}, {%4,%5,%6,%7}, {%8,%9}, {%0,%1,%2,%3};"
        : "+f"(c[0]), "+f"(c[1]), "+f"(c[2]), "+f"(c[3])
        : "r"(a0), "r"(a1), "r"(a2), "r"(a3), "r"(b0), "r"(b1));
}

// split a float into bf16 hi/lo
__device__ __forceinline__ void split1(float f, unsigned short &h, unsigned short &l) {
    __nv_bfloat16 hb = __float2bfloat16(f);
    __nv_bfloat16 lb = __float2bfloat16(f - __bfloat162float(hb));
    h = __bfloat16_as_ushort(hb);
    l = __bfloat16_as_ushort(lb);
}

__global__ __launch_bounds__(THREADS, 3)
void conv1d_local_mma(const float* __restrict__ x,
                      const float* __restrict__ w,
                      float* __restrict__ out)
{
    extern __shared__ char smem[];
    const unsigned smem_u = (unsigned)__cvta_generic_to_shared(smem);
    const int tid  = threadIdx.x;
    const int lane = tid & 31;
    const int warp = tid >> 5;
    const int sg   = warp >> 2;          // s within CTA (0..1)
    const int q    = warp & 3;           // M-slice (rows q*16 .. q*16+15)
    const int s0   = blockIdx.x * STILE;
    const int grp  = tid >> 3;           // o-group / b-group id for bank rotation

    float acc[4][4];
    #pragma unroll
    for (int a = 0; a < 4; ++a)
        #pragma unroll
        for (int qq = 0; qq < 4; ++qq) acc[a][qq] = 0.f;

    const unsigned Ah = smem_u + SM_A    + sg * A_TILE;
    const unsigned Al = smem_u + SM_A_LO + sg * A_TILE;
    const unsigned Bh = smem_u + SM_B    + sg * B_TILE;
    const unsigned Bl = smem_u + SM_B_LO + sg * B_TILE;

    #pragma unroll 1
    for (int c = 0; c < NCHUNK; ++c) {
        __syncthreads();   // all warps done reading tiles(c-1)

        // ---- w: 512 runs (o, il); 2 per thread. Each run = 14 floats
        // (both s, 7 k each), 8B-aligned -> 7 x __ldg float2.
        #pragma unroll
        for (int m = 0; m < 2; ++m) {
            int r  = tid + THREADS * m;
            int o  = r >> 3, il = r & 7;
            int i  = c * ICHUNK + il;
            const float2* src = reinterpret_cast<const float2*>(
                w + (((size_t)(o * IC_ + i) * S_ + s0) * KW_));
            float v[14];
            #pragma unroll
            for (int p = 0; p < 7; ++p) {
                float2 t2 = __ldg(src + p);
                v[2 * p] = t2.x; v[2 * p + 1] = t2.y;
            }
            unsigned short uh[16], ul[16];
            #pragma unroll
            for (int sl = 0; sl < 2; ++sl) {
                #pragma unroll
                for (int k = 0; k < 7; ++k)
                    split1(v[sl * 7 + k], uh[sl * 8 + k], ul[sl * 8 + k]);
                uh[sl * 8 + 7] = 0; ul[sl * 8 + 7] = 0;
            }
            unsigned chunkoff = (unsigned)(o * 128 + ((il ^ (o & 7)) << 4));
            #pragma unroll
            for (int sl = 0; sl < 2; ++sl) {
                char* ph = smem + SM_A    + sl * A_TILE + chunkoff;
                char* pl = smem + SM_A_LO + sl * A_TILE + chunkoff;
                #pragma unroll
                for (int n = 0; n < 4; ++n) {
                    int j2 = (grp + n) & 3;   // cross-group bank rotation
                    unsigned wh2 = (unsigned)uh[sl*8 + 2*j2] | ((unsigned)uh[sl*8 + 2*j2+1] << 16);
                    unsigned wl2 = (unsigned)ul[sl*8 + 2*j2] | ((unsigned)ul[sl*8 + 2*j2+1] << 16);
                    *reinterpret_cast<unsigned*>(ph + 4*j2) = wh2;
                    *reinterpret_cast<unsigned*>(pl + 4*j2) = wl2;
                }
            }
        }
        // ---- x: 256 runs (b, il); 1 per thread. Run = 8 floats (s0..s0+7),
        // 8B-aligned -> 4 x __ldg float2. kk slot7 zero.
        {
            int r  = tid;
            int b  = r >> 3, il = r & 7;
            int i  = c * ICHUNK + il;
            const float2* src = reinterpret_cast<const float2*>(
                x + ((size_t)(b * IC_ + i) * L_ + s0));
            float v[8];
            #pragma unroll
            for (int p = 0; p < 4; ++p) {
                float2 t2 = __ldg(src + p);
                v[2 * p] = t2.x; v[2 * p + 1] = t2.y;
            }
            unsigned short uh[16], ul[16];
            #pragma unroll
            for (int sl = 0; sl < 2; ++sl) {
                #pragma unroll
                for (int k = 0; k < 7; ++k)
                    split1(v[sl + k], uh[sl * 8 + k], ul[sl * 8 + k]);
                uh[sl * 8 + 7] = 0; ul[sl * 8 + 7] = 0;
            }
            unsigned chunkoff = (unsigned)(b * 128 + ((il ^ (b & 7)) << 4));
            #pragma unroll
            for (int sl = 0; sl < 2; ++sl) {
                char* ph = smem + SM_B    + sl * B_TILE + chunkoff;
                char* pl = smem + SM_B_LO + sl * B_TILE + chunkoff;
                #pragma unroll
                for (int n = 0; n < 4; ++n) {
                    int j2 = (grp + n) & 3;
                    unsigned wh2 = (unsigned)uh[sl*8 + 2*j2] | ((unsigned)uh[sl*8 + 2*j2+1] << 16);
                    unsigned wl2 = (unsigned)ul[sl*8 + 2*j2] | ((unsigned)ul[sl*8 + 2*j2+1] << 16);
                    *reinterpret_cast<unsigned*>(ph + 4*j2) = wh2;
                    *reinterpret_cast<unsigned*>(pl + 4*j2) = wl2;
                }
            }
        }
        __syncthreads();   // tiles(c) ready

        // ---- mma phase: warp's 16-row slice of s-GEMM sg, K'=64 -> 4 ksteps
        #pragma unroll
        for (int ks = 0; ks < 4; ++ks) {
            unsigned bh[8], bl[8];
            #pragma unroll
            for (int nt2 = 0; nt2 < 2; ++nt2) {
                int row = nt2 * 16 + ((lane >> 4) << 3) + (lane & 7);
                int ch  = 2 * ks + ((lane >> 3) & 1);
                unsigned byte = (unsigned)(row * 128 + ((ch ^ (row & 7)) << 4));
                ldsm4(Bh + byte, bh[nt2*4+0], bh[nt2*4+1], bh[nt2*4+2], bh[nt2*4+3]);
                ldsm4(Bl + byte, bl[nt2*4+0], bl[nt2*4+1], bl[nt2*4+2], bl[nt2*4+3]);
            }
            {
                int row = q * 16 + (lane & 15);
                int ch  = 2 * ks + (lane >> 4);
                unsigned byte = (unsigned)(row * 128 + ((ch ^ (row & 7)) << 4));
                unsigned a0, a1, a2, a3, c0, c1, c2, c3;
                ldsm4(Ah + byte, a0, a1, a2, a3);
                ldsm4(Al + byte, c0, c1, c2, c3);
                #pragma unroll
                for (int nt = 0; nt < 4; ++nt) {
                    unsigned b0 = bh[nt*2], b1 = bh[nt*2+1];
                    unsigned e0 = bl[nt*2], e1 = bl[nt*2+1];
                    mma16816(acc[nt], a0, a1, a2, a3, b0, b1); // wh*xh
                    mma16816(acc[nt], c0, c1, c2, c3, b0, b1); // wl*xh
                    mma16816(acc[nt], a0, a1, a2, a3, e0, e1); // wh*xl
                }
            }
        }
    }

    // ---- epilogue: direct STG, full coverage
    const int s_g  = s0 + sg;
    const int row0 = q * 16 + (lane >> 2);
    #pragma unroll
    for (int nt = 0; nt < 4; ++nt) {
        int col0 = nt * 8 + (lane & 3) * 2;
        out[(size_t)(col0    ) * (OC_ * S_) + (size_t)(row0    ) * S_ + s_g] = acc[nt][0];
        out[(size_t)(col0 + 1) * (OC_ * S_) + (size_t)(row0    ) * S_ + s_g] = acc[nt][1];
        out[(size_t)(col0    ) * (OC_ * S_) + (size_t)(row0 + 8) * S_ + s_g] = acc[nt][2];
        out[(size_t)(col0 + 1) * (OC_ * S_) + (size_t)(row0 + 8) * S_ + s_g] = acc[nt][3];
    }
}

extern "C" void kernel_launch(void* const* d_in, const int* in_sizes, int n_in,
                              void* d_out, int out_size)
{
    const float* x = (const float*)d_in[0];
    const float* w = (const float*)d_in[1];
    float* out = (float*)d_out;

    cudaFuncSetAttribute(conv1d_local_mma,
                         cudaFuncAttributeMaxDynamicSharedMemorySize, SMEM_TOTAL);

    conv1d_local_mma<<<S_ / STILE, THREADS, SMEM_TOTAL>>>(x, w, out);
}